// round 1
// baseline (speedup 1.0000x reference)
#include <cuda_runtime.h>
#include <math.h>

// Problem constants
#define BATCH 256
#define GSZ   60
#define KSZ   13
#define NTOT  (BATCH * GSZ)   // 15360

// Output layout (tuple flattened, all float32):
// feats0, feats1, eqv0, eqv1, inv0, inv1, ability, true_idx, pre_idxs
#define OFF_F0 0
#define OFF_F1 491520
#define OFF_E0 983040
#define OFF_E1 1474560
#define OFF_I0 1966080
#define OFF_I1 1974272
#define OFF_AB 1982464
#define OFF_TI 1982465
#define OFF_PI 1982721

// Scratch (device globals; allocation APIs are forbidden)
__device__ float g_Z[13 * 512 * NTOT];     // 409 MB, max layer Z
__device__ float g_d [BATCH * 256 * GSZ];  // d (then d+fc in place)
__device__ float g_f1[BATCH * 512 * GSZ];  // fc1
__device__ float g_ep[BATCH * 32 * GSZ];   // eqv_pre
__device__ float g_eqv0[BATCH * 32 * GSZ];
__device__ float g_eqv1[BATCH * 32 * GSZ];
__device__ int   g_pre[BATCH];

// ---------------------------------------------------------------------------
// GEMM: Z[m, n] = sum_c A[m, c] * Bmat[c, n]
//   A[m, c]   = W[o, c, k]  with m = k*O + o   (W layout [O][C][13])
//   Bmat[c,n] = act[b, c, g] with n = b*60 + g (act layout [B][C][60])
// Tile 64x64x16, 256 threads, 4x4 per thread.
// ---------------------------------------------------------------------------
__global__ __launch_bounds__(256) void gemm64(
    const float* __restrict__ W, const float* __restrict__ act,
    float* __restrict__ Z, int C, int O, int M)
{
    __shared__ float As[16][64];
    __shared__ float Bs[16][64];

    const int tid = threadIdx.x;
    const int bm = blockIdx.y, bn = blockIdx.x;
    const int ml = tid & 63;        // column within tile for loads
    const int cg = tid >> 6;        // 0..3

    // A-load indices (fixed per thread)
    const int m = bm * 64 + ml;
    const bool mvalid = (m < M);
    int kk_idx = 0, o_idx = 0;
    if (mvalid) { kk_idx = m / O; o_idx = m - kk_idx * O; }
    const float* Wbase = W + ((size_t)o_idx * C) * 13 + kk_idx;

    // B-load indices (fixed per thread)
    const int n = bn * 64 + ml;
    const int bb = n / 60, gg = n - bb * 60;
    const float* actb = act + (size_t)bb * C * 60 + gg;

    const int ty = tid >> 4, tx = tid & 15;
    float acc[4][4] = {};

    for (int c0 = 0; c0 < C; c0 += 16) {
        #pragma unroll
        for (int i = 0; i < 4; ++i) {
            const int cl = cg * 4 + i;
            float av = 0.f;
            if (mvalid) av = Wbase[(size_t)(c0 + cl) * 13];
            As[cl][ml] = av;
            Bs[cl][ml] = actb[(size_t)(c0 + cl) * 60];
        }
        __syncthreads();

        #pragma unroll
        for (int kk = 0; kk < 16; ++kk) {
            float4 a4 = *reinterpret_cast<const float4*>(&As[kk][ty * 4]);
            float4 b4 = *reinterpret_cast<const float4*>(&Bs[kk][tx * 4]);
            float av[4] = {a4.x, a4.y, a4.z, a4.w};
            float bv[4] = {b4.x, b4.y, b4.z, b4.w};
            #pragma unroll
            for (int i = 0; i < 4; ++i)
                #pragma unroll
                for (int j = 0; j < 4; ++j)
                    acc[i][j] += av[i] * bv[j];
        }
        __syncthreads();
    }

    #pragma unroll
    for (int i = 0; i < 4; ++i) {
        const int mo = bm * 64 + ty * 4 + i;
        if (mo < M) {
            float4 v = make_float4(acc[i][0], acc[i][1], acc[i][2], acc[i][3]);
            *reinterpret_cast<float4*>(&Z[(size_t)mo * NTOT + bn * 64 + tx * 4]) = v;
        }
    }
}

// ---------------------------------------------------------------------------
// Epilogue: out[b,o,g] = f( bias[o] + sum_k Z[(k*O+o), b*60 + nei[g*13+k]] )
// mode 0: out = s
// mode 1: out = relu(s*gamma + beta)
// mode 2: out += relu(s*gamma + beta)          (residual, in place)
// mode 3: out = relu(s*gamma + beta) + extra   (extra = feats, O==32)
// grid (O/4, B), 240 threads
// ---------------------------------------------------------------------------
__global__ __launch_bounds__(240) void ep_kernel(
    const float* __restrict__ Z, const int* __restrict__ nei,
    const float* __restrict__ bias, const float* __restrict__ gamma,
    const float* __restrict__ beta, const float* __restrict__ extra,
    float* __restrict__ out, int O, int mode)
{
    __shared__ int sn[GSZ * KSZ];
    const int tid = threadIdx.x;
    for (int i = tid; i < GSZ * KSZ; i += 240) sn[i] = nei[i];
    __syncthreads();

    const int g = tid % 60, ol = tid / 60;
    const int o = blockIdx.x * 4 + ol;
    const int b = blockIdx.y;

    float s = bias[o];
    #pragma unroll
    for (int k = 0; k < KSZ; ++k)
        s += Z[(size_t)(k * O + o) * NTOT + b * 60 + sn[g * KSZ + k]];

    const size_t oi = (size_t)b * O * 60 + (size_t)o * 60 + g;
    if (mode == 0) {
        out[oi] = s;
    } else {
        float v = fmaxf(s * gamma[o] + beta[o], 0.f);
        if (mode == 1)      out[oi] = v;
        else if (mode == 2) out[oi] += v;
        else                out[oi] = v + extra[oi];
    }
}

// ---------------------------------------------------------------------------
// finalize: inv = mean_g(ep); eqv = ep / max(||ep[b,:,g]||, 1e-4);
//           inv /= max(||inv||, 1e-4). One block per b, 64 threads.
// ---------------------------------------------------------------------------
__global__ __launch_bounds__(64) void finalize_kernel(
    const float* __restrict__ ep, float* __restrict__ eqv_store,
    float* __restrict__ out_eqv, float* __restrict__ out_inv)
{
    __shared__ float s[32 * 60];
    __shared__ float norms[60];
    __shared__ float invv[32];
    __shared__ float sninv;
    const int b = blockIdx.x, t = threadIdx.x;

    for (int i = t; i < 1920; i += 64) s[i] = ep[(size_t)b * 1920 + i];
    __syncthreads();

    if (t < 32) {
        float a = 0.f;
        for (int g = 0; g < 60; ++g) a += s[t * 60 + g];
        invv[t] = a * (1.f / 60.f);
    }
    if (t < 60) {
        float a = 0.f;
        for (int c = 0; c < 32; ++c) { float v = s[c * 60 + t]; a += v * v; }
        norms[t] = fmaxf(sqrtf(a), 1e-4f);
    }
    __syncthreads();
    if (t == 0) {
        float a = 0.f;
        for (int c = 0; c < 32; ++c) a += invv[c] * invv[c];
        sninv = fmaxf(sqrtf(a), 1e-4f);
    }
    __syncthreads();

    if (t < 32) out_inv[b * 32 + t] = invv[t] / sninv;
    for (int i = t; i < 1920; i += 64) {
        const int g = i % 60;
        const float v = s[i] / norms[g];
        eqv_store[(size_t)b * 1920 + i] = v;
        out_eqv[(size_t)b * 1920 + i]   = v;
    }
}

// ---------------------------------------------------------------------------
// des2dr: cor[b,a] = sum_{f,g} e0[b,f,permu[a*60+g]] * e1[b,f,g]; argmax_a.
// One block per b, 64 threads.
// ---------------------------------------------------------------------------
__global__ __launch_bounds__(64) void des2dr_kernel(
    const float* __restrict__ e0, const float* __restrict__ e1,
    const int* __restrict__ permu, int* __restrict__ pre)
{
    __shared__ float s0[1920], s1[1920];
    __shared__ float cor[60];
    __shared__ int sp[3600];
    const int b = blockIdx.x, t = threadIdx.x;

    for (int i = t; i < 1920; i += 64) {
        s0[i] = e0[(size_t)b * 1920 + i];
        s1[i] = e1[(size_t)b * 1920 + i];
    }
    for (int i = t; i < 3600; i += 64) sp[i] = permu[i];
    __syncthreads();

    if (t < 60) {
        float a = 0.f;
        for (int g = 0; g < 60; ++g) {
            const int p = sp[t * 60 + g];
            #pragma unroll 8
            for (int f = 0; f < 32; ++f) a += s0[f * 60 + p] * s1[f * 60 + g];
        }
        cor[t] = a;
    }
    __syncthreads();
    if (t == 0) {
        float best = cor[0]; int bi = 0;
        for (int a = 1; a < 60; ++a) if (cor[a] > best) { best = cor[a]; bi = a; }
        pre[b] = bi;
    }
}

// ability + integer outputs
__global__ __launch_bounds__(256) void final_kernel(
    const int* __restrict__ pre, const int* __restrict__ truei,
    float* __restrict__ out)
{
    __shared__ int cnt[256];
    const int t = threadIdx.x;
    cnt[t] = (pre[t] == truei[t]) ? 1 : 0;
    __syncthreads();
    for (int s = 128; s > 0; s >>= 1) {
        if (t < s) cnt[t] += cnt[t + s];
        __syncthreads();
    }
    if (t == 0) out[OFF_AB] = (float)cnt[0] / 256.f;
    out[OFF_TI + t] = (float)truei[t];
    out[OFF_PI + t] = (float)pre[t];
}

// ---------------------------------------------------------------------------
extern "C" void kernel_launch(void* const* d_in, const int* in_sizes, int n_in,
                              void* d_out, int out_size)
{
    const float* feats0 = (const float*)d_in[0];
    const float* feats1 = (const float*)d_in[1];
    const int*   truei  = (const int*)  d_in[2];
    const int*   nei    = (const int*)  d_in[3];
    const int*   permu  = (const int*)  d_in[4];
    const float* W_in = (const float*)d_in[5];  const float* b_in = (const float*)d_in[6];
    const float* W1   = (const float*)d_in[7];  const float* b1   = (const float*)d_in[8];
    const float* g1   = (const float*)d_in[9];  const float* be1  = (const float*)d_in[10];
    const float* W2   = (const float*)d_in[11]; const float* b2   = (const float*)d_in[12];
    const float* g2   = (const float*)d_in[13]; const float* be2  = (const float*)d_in[14];
    const float* Wo   = (const float*)d_in[15]; const float* bo   = (const float*)d_in[16];
    const float* go   = (const float*)d_in[17]; const float* beo  = (const float*)d_in[18];
    float* out = (float*)d_out;

    float *Z, *dbuf, *f1, *epb, *e0, *e1;
    int* pre;
    cudaGetSymbolAddress((void**)&Z,    g_Z);
    cudaGetSymbolAddress((void**)&dbuf, g_d);
    cudaGetSymbolAddress((void**)&f1,   g_f1);
    cudaGetSymbolAddress((void**)&epb,  g_ep);
    cudaGetSymbolAddress((void**)&e0,   g_eqv0);
    cudaGetSymbolAddress((void**)&e1,   g_eqv1);
    cudaGetSymbolAddress((void**)&pre,  g_pre);

    // echo inputs
    cudaMemcpyAsync(out + OFF_F0, feats0, (size_t)491520 * 4, cudaMemcpyDeviceToDevice, 0);
    cudaMemcpyAsync(out + OFF_F1, feats1, (size_t)491520 * 4, cudaMemcpyDeviceToDevice, 0);

    const dim3 blk256(256), blk240(240);

    auto run_net = [&](const float* feats, float* eqv_store,
                       float* out_eqv, float* out_inv) {
        // conv_in: C=32 -> O=256, M = 13*256 = 3328
        gemm64<<<dim3(NTOT / 64, 3328 / 64), blk256>>>(W_in, feats, Z, 32, 256, 3328);
        ep_kernel<<<dim3(256 / 4, BATCH), blk240>>>(Z, nei, b_in, b_in, b_in, nullptr, dbuf, 256, 0);
        // layer1: 256 -> 512, M = 6656
        gemm64<<<dim3(NTOT / 64, 6656 / 64), blk256>>>(W1, dbuf, Z, 256, 512, 6656);
        ep_kernel<<<dim3(512 / 4, BATCH), blk240>>>(Z, nei, b1, g1, be1, nullptr, f1, 512, 1);
        // layer2: 512 -> 256, residual into dbuf
        gemm64<<<dim3(NTOT / 64, 3328 / 64), blk256>>>(W2, f1, Z, 512, 256, 3328);
        ep_kernel<<<dim3(256 / 4, BATCH), blk240>>>(Z, nei, b2, g2, be2, nullptr, dbuf, 256, 2);
        // conv_out: 256 -> 32, M = 416 (7 M-blocks w/ guard), + feats add
        gemm64<<<dim3(NTOT / 64, (416 + 63) / 64), blk256>>>(Wo, dbuf, Z, 256, 32, 416);
        ep_kernel<<<dim3(32 / 4, BATCH), blk240>>>(Z, nei, bo, go, beo, feats, epb, 32, 3);
        // norms
        finalize_kernel<<<BATCH, 64>>>(epb, eqv_store, out_eqv, out_inv);
    };

    run_net(feats0, e0, out + OFF_E0, out + OFF_I0);
    run_net(feats1, e1, out + OFF_E1, out + OFF_I1);

    des2dr_kernel<<<BATCH, 64>>>(e0, e1, permu, pre);
    final_kernel<<<1, 256>>>(pre, truei, out);
}

// round 4
// speedup vs baseline: 1.0002x; 1.0002x over previous
#include <cuda_runtime.h>
#include <math.h>

// Problem constants
#define BATCH 256
#define GSZ   60
#define KSZ   13
#define NTOT  (BATCH * GSZ)   // 15360

// Output layout (tuple flattened, all float32):
// feats0, feats1, eqv0, eqv1, inv0, inv1, ability, true_idx, pre_idxs
#define OFF_F0 0
#define OFF_F1 491520
#define OFF_E0 983040
#define OFF_E1 1474560
#define OFF_I0 1966080
#define OFF_I1 1974272
#define OFF_AB 1982464
#define OFF_TI 1982465
#define OFF_PI 1982721

// Scratch (device globals; allocation APIs are forbidden)
__device__ float g_Z[13 * 512 * NTOT];     // 409 MB, max layer Z
__device__ float g_d [BATCH * 256 * GSZ];  // d (then d+fc in place)
__device__ float g_f1[BATCH * 512 * GSZ];  // fc1
__device__ float g_ep[BATCH * 32 * GSZ];   // eqv_pre
__device__ float g_eqv0[BATCH * 32 * GSZ];
__device__ float g_eqv1[BATCH * 32 * GSZ];
__device__ int   g_pre[BATCH];

// ---------------------------------------------------------------------------
// GEMM: Z[m, n] = sum_c A[m, c] * Bmat[c, n]
//   A[m, c]   = W[o, c, k]  with m = k*O + o   (W layout [O][C][13])
//   Bmat[c,n] = act[b, c, g] with n = b*60 + g (act layout [B][C][60])
// Tile 64x64x16, 256 threads, 4x4 per thread.
// ---------------------------------------------------------------------------
__global__ __launch_bounds__(256) void gemm64(
    const float* __restrict__ W, const float* __restrict__ act,
    float* __restrict__ Z, int C, int O, int M)
{
    __shared__ float As[16][64];
    __shared__ float Bs[16][64];

    const int tid = threadIdx.x;
    const int bm = blockIdx.y, bn = blockIdx.x;
    const int ml = tid & 63;        // column within tile for loads
    const int cg = tid >> 6;        // 0..3

    // A-load indices (fixed per thread)
    const int m = bm * 64 + ml;
    const bool mvalid = (m < M);
    int kk_idx = 0, o_idx = 0;
    if (mvalid) { kk_idx = m / O; o_idx = m - kk_idx * O; }
    const float* Wbase = W + ((size_t)o_idx * C) * 13 + kk_idx;

    // B-load indices (fixed per thread)
    const int n = bn * 64 + ml;
    const int bb = n / 60, gg = n - bb * 60;
    const float* actb = act + (size_t)bb * C * 60 + gg;

    const int ty = tid >> 4, tx = tid & 15;
    float acc[4][4] = {};

    for (int c0 = 0; c0 < C; c0 += 16) {
        #pragma unroll
        for (int i = 0; i < 4; ++i) {
            const int cl = cg * 4 + i;
            float av = 0.f;
            if (mvalid) av = Wbase[(size_t)(c0 + cl) * 13];
            As[cl][ml] = av;
            Bs[cl][ml] = actb[(size_t)(c0 + cl) * 60];
        }
        __syncthreads();

        #pragma unroll
        for (int kk = 0; kk < 16; ++kk) {
            float4 a4 = *reinterpret_cast<const float4*>(&As[kk][ty * 4]);
            float4 b4 = *reinterpret_cast<const float4*>(&Bs[kk][tx * 4]);
            float av[4] = {a4.x, a4.y, a4.z, a4.w};
            float bv[4] = {b4.x, b4.y, b4.z, b4.w};
            #pragma unroll
            for (int i = 0; i < 4; ++i)
                #pragma unroll
                for (int j = 0; j < 4; ++j)
                    acc[i][j] += av[i] * bv[j];
        }
        __syncthreads();
    }

    #pragma unroll
    for (int i = 0; i < 4; ++i) {
        const int mo = bm * 64 + ty * 4 + i;
        if (mo < M) {
            float4 v = make_float4(acc[i][0], acc[i][1], acc[i][2], acc[i][3]);
            *reinterpret_cast<float4*>(&Z[(size_t)mo * NTOT + bn * 64 + tx * 4]) = v;
        }
    }
}

// ---------------------------------------------------------------------------
// Epilogue: out[b,o,g] = f( bias[o] + sum_k Z[(k*O+o), b*60 + nei[g*13+k]] )
// mode 0: out = s
// mode 1: out = relu(s*gamma + beta)
// mode 2: out += relu(s*gamma + beta)          (residual, in place)
// mode 3: out = relu(s*gamma + beta) + extra   (extra = feats, O==32)
// grid (O/4, B), 240 threads
// ---------------------------------------------------------------------------
__global__ __launch_bounds__(240) void ep_kernel(
    const float* __restrict__ Z, const int* __restrict__ nei,
    const float* __restrict__ bias, const float* __restrict__ gamma,
    const float* __restrict__ beta, const float* __restrict__ extra,
    float* __restrict__ out, int O, int mode)
{
    __shared__ int sn[GSZ * KSZ];
    const int tid = threadIdx.x;
    for (int i = tid; i < GSZ * KSZ; i += 240) sn[i] = nei[i];
    __syncthreads();

    const int g = tid % 60, ol = tid / 60;
    const int o = blockIdx.x * 4 + ol;
    const int b = blockIdx.y;

    float s = bias[o];
    #pragma unroll
    for (int k = 0; k < KSZ; ++k)
        s += Z[(size_t)(k * O + o) * NTOT + b * 60 + sn[g * KSZ + k]];

    const size_t oi = (size_t)b * O * 60 + (size_t)o * 60 + g;
    if (mode == 0) {
        out[oi] = s;
    } else {
        float v = fmaxf(s * gamma[o] + beta[o], 0.f);
        if (mode == 1)      out[oi] = v;
        else if (mode == 2) out[oi] += v;
        else                out[oi] = v + extra[oi];
    }
}

// ---------------------------------------------------------------------------
// finalize: inv = mean_g(ep); eqv = ep / max(||ep[b,:,g]||, 1e-4);
//           inv /= max(||inv||, 1e-4). One block per b, 64 threads.
// ---------------------------------------------------------------------------
__global__ __launch_bounds__(64) void finalize_kernel(
    const float* __restrict__ ep, float* __restrict__ eqv_store,
    float* __restrict__ out_eqv, float* __restrict__ out_inv)
{
    __shared__ float s[32 * 60];
    __shared__ float norms[60];
    __shared__ float invv[32];
    __shared__ float sninv;
    const int b = blockIdx.x, t = threadIdx.x;

    for (int i = t; i < 1920; i += 64) s[i] = ep[(size_t)b * 1920 + i];
    __syncthreads();

    if (t < 32) {
        float a = 0.f;
        for (int g = 0; g < 60; ++g) a += s[t * 60 + g];
        invv[t] = a * (1.f / 60.f);
    }
    if (t < 60) {
        float a = 0.f;
        for (int c = 0; c < 32; ++c) { float v = s[c * 60 + t]; a += v * v; }
        norms[t] = fmaxf(sqrtf(a), 1e-4f);
    }
    __syncthreads();
    if (t == 0) {
        float a = 0.f;
        for (int c = 0; c < 32; ++c) a += invv[c] * invv[c];
        sninv = fmaxf(sqrtf(a), 1e-4f);
    }
    __syncthreads();

    if (t < 32) out_inv[b * 32 + t] = invv[t] / sninv;
    for (int i = t; i < 1920; i += 64) {
        const int g = i % 60;
        const float v = s[i] / norms[g];
        eqv_store[(size_t)b * 1920 + i] = v;
        out_eqv[(size_t)b * 1920 + i]   = v;
    }
}

// ---------------------------------------------------------------------------
// des2dr: cor[b,a] = sum_{f,g} e0[b,f,permu[a*60+g]] * e1[b,f,g]; argmax_a.
// One block per b, 64 threads.
// ---------------------------------------------------------------------------
__global__ __launch_bounds__(64) void des2dr_kernel(
    const float* __restrict__ e0, const float* __restrict__ e1,
    const int* __restrict__ permu, int* __restrict__ pre)
{
    __shared__ float s0[1920], s1[1920];
    __shared__ float cor[60];
    __shared__ int sp[3600];
    const int b = blockIdx.x, t = threadIdx.x;

    for (int i = t; i < 1920; i += 64) {
        s0[i] = e0[(size_t)b * 1920 + i];
        s1[i] = e1[(size_t)b * 1920 + i];
    }
    for (int i = t; i < 3600; i += 64) sp[i] = permu[i];
    __syncthreads();

    if (t < 60) {
        float a = 0.f;
        for (int g = 0; g < 60; ++g) {
            const int p = sp[t * 60 + g];
            #pragma unroll 8
            for (int f = 0; f < 32; ++f) a += s0[f * 60 + p] * s1[f * 60 + g];
        }
        cor[t] = a;
    }
    __syncthreads();
    if (t == 0) {
        float best = cor[0]; int bi = 0;
        for (int a = 1; a < 60; ++a) if (cor[a] > best) { best = cor[a]; bi = a; }
        pre[b] = bi;
    }
}

// ability + integer outputs
__global__ __launch_bounds__(256) void final_kernel(
    const int* __restrict__ pre, const int* __restrict__ truei,
    float* __restrict__ out)
{
    __shared__ int cnt[256];
    const int t = threadIdx.x;
    cnt[t] = (pre[t] == truei[t]) ? 1 : 0;
    __syncthreads();
    for (int s = 128; s > 0; s >>= 1) {
        if (t < s) cnt[t] += cnt[t + s];
        __syncthreads();
    }
    if (t == 0) out[OFF_AB] = (float)cnt[0] / 256.f;
    out[OFF_TI + t] = (float)truei[t];
    out[OFF_PI + t] = (float)pre[t];
}

// ---------------------------------------------------------------------------
extern "C" void kernel_launch(void* const* d_in, const int* in_sizes, int n_in,
                              void* d_out, int out_size)
{
    const float* feats0 = (const float*)d_in[0];
    const float* feats1 = (const float*)d_in[1];
    const int*   truei  = (const int*)  d_in[2];
    const int*   nei    = (const int*)  d_in[3];
    const int*   permu  = (const int*)  d_in[4];
    const float* W_in = (const float*)d_in[5];  const float* b_in = (const float*)d_in[6];
    const float* W1   = (const float*)d_in[7];  const float* b1   = (const float*)d_in[8];
    const float* g1   = (const float*)d_in[9];  const float* be1  = (const float*)d_in[10];
    const float* W2   = (const float*)d_in[11]; const float* b2   = (const float*)d_in[12];
    const float* g2   = (const float*)d_in[13]; const float* be2  = (const float*)d_in[14];
    const float* Wo   = (const float*)d_in[15]; const float* bo   = (const float*)d_in[16];
    const float* go   = (const float*)d_in[17]; const float* beo  = (const float*)d_in[18];
    float* out = (float*)d_out;

    float *Z, *dbuf, *f1, *epb, *e0, *e1;
    int* pre;
    cudaGetSymbolAddress((void**)&Z,    g_Z);
    cudaGetSymbolAddress((void**)&dbuf, g_d);
    cudaGetSymbolAddress((void**)&f1,   g_f1);
    cudaGetSymbolAddress((void**)&epb,  g_ep);
    cudaGetSymbolAddress((void**)&e0,   g_eqv0);
    cudaGetSymbolAddress((void**)&e1,   g_eqv1);
    cudaGetSymbolAddress((void**)&pre,  g_pre);

    // echo inputs
    cudaMemcpyAsync(out + OFF_F0, feats0, (size_t)491520 * 4, cudaMemcpyDeviceToDevice, 0);
    cudaMemcpyAsync(out + OFF_F1, feats1, (size_t)491520 * 4, cudaMemcpyDeviceToDevice, 0);

    const dim3 blk256(256), blk240(240);

    auto run_net = [&](const float* feats, float* eqv_store,
                       float* out_eqv, float* out_inv) {
        // conv_in: C=32 -> O=256, M = 13*256 = 3328
        gemm64<<<dim3(NTOT / 64, 3328 / 64), blk256>>>(W_in, feats, Z, 32, 256, 3328);
        ep_kernel<<<dim3(256 / 4, BATCH), blk240>>>(Z, nei, b_in, b_in, b_in, nullptr, dbuf, 256, 0);
        // layer1: 256 -> 512, M = 6656
        gemm64<<<dim3(NTOT / 64, 6656 / 64), blk256>>>(W1, dbuf, Z, 256, 512, 6656);
        ep_kernel<<<dim3(512 / 4, BATCH), blk240>>>(Z, nei, b1, g1, be1, nullptr, f1, 512, 1);
        // layer2: 512 -> 256, residual into dbuf
        gemm64<<<dim3(NTOT / 64, 3328 / 64), blk256>>>(W2, f1, Z, 512, 256, 3328);
        ep_kernel<<<dim3(256 / 4, BATCH), blk240>>>(Z, nei, b2, g2, be2, nullptr, dbuf, 256, 2);
        // conv_out: 256 -> 32, M = 416 (7 M-blocks w/ guard), + feats add
        gemm64<<<dim3(NTOT / 64, (416 + 63) / 64), blk256>>>(Wo, dbuf, Z, 256, 32, 416);
        ep_kernel<<<dim3(32 / 4, BATCH), blk240>>>(Z, nei, bo, go, beo, feats, epb, 32, 3);
        // norms
        finalize_kernel<<<BATCH, 64>>>(epb, eqv_store, out_eqv, out_inv);
    };

    run_net(feats0, e0, out + OFF_E0, out + OFF_I0);
    run_net(feats1, e1, out + OFF_E1, out + OFF_I1);

    des2dr_kernel<<<BATCH, 64>>>(e0, e1, permu, pre);
    final_kernel<<<1, 256>>>(pre, truei, out);
}

// round 8
// speedup vs baseline: 2.5748x; 2.5744x over previous
#include <cuda_runtime.h>
#include <cuda_bf16.h>
#include <math.h>
#include <stdint.h>

#define BATCH 256
#define GSZ   60
#define KSZ   13
#define NTOT  (BATCH * GSZ)   // 15360

#define OFF_F0 0
#define OFF_F1 491520
#define OFF_E0 983040
#define OFF_E1 1474560
#define OFF_I0 1966080
#define OFF_I1 1974272
#define OFF_AB 1982464
#define OFF_TI 1982465
#define OFF_PI 1982721

// ---------------------------------------------------------------------------
// Device scratch (allocation APIs forbidden).
// Weights: Wp[o][s][hi 64 bf16 | lo 64 bf16], s = j*13 + k (chunk-major).
// Acts:    actP[n][j][hi 64 | lo 64]  (n = b*60+g position, j = channel chunk)
// ---------------------------------------------------------------------------
__device__ __nv_bfloat16 g_WpI[256 * 13 * 128];
__device__ __nv_bfloat16 g_Wp1[512 * 52 * 128];
__device__ __nv_bfloat16 g_Wp2[256 * 104 * 128];
__device__ __nv_bfloat16 g_WpO[128 * 52 * 128];
__device__ __nv_bfloat16 g_fP [NTOT * 1 * 128];
__device__ __nv_bfloat16 g_dP [NTOT * 4 * 128];
__device__ __nv_bfloat16 g_f1P[NTOT * 8 * 128];
__device__ __nv_bfloat16 g_d2P[NTOT * 4 * 128];
__device__ float g_dT32[NTOT * 256];
__device__ float g_epT [NTOT * 32];
__device__ float g_e0  [BATCH * 32 * GSZ];
__device__ float g_e1  [BATCH * 32 * GSZ];
__device__ int   g_pre [BATCH];

// ---- helpers ----
__device__ __forceinline__ uint32_t smem_u32(const void* p) {
    uint32_t a;
    asm("{ .reg .u64 t; cvta.to.shared.u64 t, %1; cvt.u32.u64 %0, t; }" : "=r"(a) : "l"(p));
    return a;
}
#define SWZ(x) ((x) ^ (((x) >> 3) & 0x70))

__device__ __forceinline__ void cpasync16(uint32_t dst, const void* src) {
    asm volatile("cp.async.ca.shared.global [%0], [%1], 16;" :: "r"(dst), "l"(src) : "memory");
}
__device__ __forceinline__ void cp_commit() {
    asm volatile("cp.async.commit_group;" ::: "memory");
}
__device__ __forceinline__ void cp_wait2() {
    asm volatile("cp.async.wait_group 2;" ::: "memory");
}
__device__ __forceinline__ void ldsm4(uint32_t* r, uint32_t a) {
    asm volatile("ldmatrix.sync.aligned.m8n8.x4.shared.b16 {%0,%1,%2,%3}, [%4];"
                 : "=r"(r[0]), "=r"(r[1]), "=r"(r[2]), "=r"(r[3]) : "r"(a));
}
__device__ __forceinline__ void ldsm2(uint32_t* r, uint32_t a) {
    asm volatile("ldmatrix.sync.aligned.m8n8.x2.shared.b16 {%0,%1}, [%2];"
                 : "=r"(r[0]), "=r"(r[1]) : "r"(a));
}
__device__ __forceinline__ void mma_bf(float* d, const uint32_t* a, const uint32_t* b) {
    asm volatile(
        "mma.sync.aligned.m16n8k16.row.col.f32.bf16.bf16.f32 "
        "{%0,%1,%2,%3},{%4,%5,%6,%7},{%8,%9},{%0,%1,%2,%3};"
        : "+f"(d[0]), "+f"(d[1]), "+f"(d[2]), "+f"(d[3])
        : "r"(a[0]), "r"(a[1]), "r"(a[2]), "r"(a[3]), "r"(b[0]), "r"(b[1]));
}

__device__ __forceinline__ void split_bf(float v, __nv_bfloat16& h, __nv_bfloat16& l) {
    h = __float2bfloat16(v);
    l = __float2bfloat16(v - __bfloat162float(h));
}

// ---- prep: W[o][cr][k] -> Wp[o][s][hi64|lo64], s=j*13+k, cr=j*64+c ----
__global__ __launch_bounds__(256) void prep_w(
    __nv_bfloat16* __restrict__ dst, const float* __restrict__ W,
    int Oreal, int Creal, int nstages)
{
    int idx = blockIdx.x * 256 + threadIdx.x;
    int c = idx & 63;
    int s = (idx >> 6) % nstages;
    int o = idx / (64 * nstages);
    int k = s % 13, j = s / 13;
    int cr = j * 64 + c;
    float v = 0.f;
    if (o < Oreal && cr < Creal) v = W[((size_t)o * Creal + cr) * 13 + k];
    __nv_bfloat16 h, l; split_bf(v, h, l);
    size_t base = ((size_t)o * nstages + s) * 128;
    dst[base + c] = h;
    dst[base + 64 + c] = l;
}

// ---- prep: feats[b][c][g] -> fP[n][hi64|lo64] (c>=32 zero) ----
__global__ __launch_bounds__(256) void prep_feats(
    __nv_bfloat16* __restrict__ dst, const float* __restrict__ f)
{
    int idx = blockIdx.x * 256 + threadIdx.x;   // < 15360*64
    int c = idx & 63;
    int n = idx >> 6;
    int b = n / 60, g = n - b * 60;
    float v = (c < 32) ? f[(size_t)b * 1920 + c * 60 + g] : 0.f;
    __nv_bfloat16 h, l; split_bf(v, h, l);
    size_t base = (size_t)n * 128;
    dst[base + c] = h;
    dst[base + 64 + c] = l;
}

// ---------------------------------------------------------------------------
// Gather-fused GEMM, mma.sync bf16 3-pass hi/lo split.
// CTA tile M=128 x N=128; 8 warps (2M x 4N), warp tile 64x32.
// Stage = one (chunk j, k) pair: 64 channels; NSTAGE=3 cp.async pipeline.
// ---------------------------------------------------------------------------
#define NSTAGE   3
#define STG      65536
#define SM_BUF   8192
#define SMEM_DYN (SM_BUF + NSTAGE * STG)   // 204800

__global__ __launch_bounds__(256, 1) void gf_gemm(
    const __nv_bfloat16* __restrict__ Wp, const __nv_bfloat16* __restrict__ actP,
    int nchB, int nstages, const int* __restrict__ nei, int mode,
    const float* __restrict__ bias, const float* __restrict__ gamma,
    const float* __restrict__ beta, const float* __restrict__ dres,
    const float* __restrict__ feats, float* __restrict__ out32,
    __nv_bfloat16* __restrict__ actOut, int nchO)
{
    extern __shared__ __align__(1024) char smem[];
    int* lut = (int*)smem;                    // [13][128]
    const uint32_t su = smem_u32(smem);
    const int tid = threadIdx.x;
    const int warp = tid >> 5, lane = tid & 31;
    const int n0 = blockIdx.x * 128;
    const int m0 = blockIdx.y * 128;

    if (tid < 128) {
        const int n = n0 + tid;
        const int b = n / 60, g = n - b * 60;
        #pragma unroll
        for (int k = 0; k < KSZ; ++k)
            lut[k * 128 + tid] = b * 60 + nei[g * KSZ + k];
    }
    __syncthreads();

    const int row = tid >> 1;          // 0..127
    const int half = tid & 1;          // 0: hi plane, 1: lo plane

    auto load_stage = [&](int s) {
        const uint32_t bufs = su + SM_BUF + (uint32_t)(s % NSTAGE) * STG;
        // A: Wp row (m0+row), stage s, 256B (hi|lo)
        {
            const char* src = (const char*)(Wp + ((size_t)(m0 + row) * nstages + s) * 128)
                              + half * 128;
            const uint32_t dst = bufs + half * 16384;
            #pragma unroll
            for (int c = 0; c < 8; ++c)
                cpasync16(dst + SWZ((uint32_t)(row * 128 + c * 16)), src + c * 16);
        }
        // B: gathered act row, chunk j = s/13, k = s%13
        {
            const int k = s % 13, j = s / 13;
            const int sr = lut[k * 128 + row];
            const char* src = (const char*)(actP + ((size_t)sr * nchB + j) * 128)
                              + half * 128;
            const uint32_t dst = bufs + 32768 + half * 16384;
            #pragma unroll
            for (int c = 0; c < 8; ++c)
                cpasync16(dst + SWZ((uint32_t)(row * 128 + c * 16)), src + c * 16);
        }
    };

    // prologue
    for (int s = 0; s < NSTAGE; ++s) {
        if (s < nstages) load_stage(s);
        cp_commit();
    }

    const int wm = warp >> 2;          // 0..1
    const int wn = warp & 3;           // 0..3
    float acc[4][4][4] = {};

    const uint32_t arow = (uint32_t)(wm * 64 + (lane & 15));
    const uint32_t acolx = (uint32_t)((lane >> 4) * 16);
    const uint32_t brow = (uint32_t)(wn * 32 + (lane & 7));
    const uint32_t bcolx = (uint32_t)(((lane >> 3) & 1) * 16);

    for (int s = 0; s < nstages; ++s) {
        cp_wait2();
        __syncthreads();
        const uint32_t bufs = su + SM_BUF + (uint32_t)(s % NSTAGE) * STG;
        const uint32_t Ah = bufs, Al = bufs + 16384, Bh = bufs + 32768, Bl = bufs + 49152;

        #pragma unroll
        for (int ks = 0; ks < 4; ++ks) {
            const uint32_t kb = ks * 32;
            uint32_t ah[4][4], al[4][4], bh[4][2], bl[4][2];
            #pragma unroll
            for (int mt = 0; mt < 4; ++mt) {
                const uint32_t off = SWZ((arow + mt * 16) * 128 + kb + acolx);
                ldsm4(ah[mt], Ah + off);
                ldsm4(al[mt], Al + off);
            }
            #pragma unroll
            for (int nt = 0; nt < 4; ++nt) {
                const uint32_t off = SWZ((brow + nt * 8) * 128 + kb + bcolx);
                ldsm2(bh[nt], Bh + off);
                ldsm2(bl[nt], Bl + off);
            }
            #pragma unroll
            for (int mt = 0; mt < 4; ++mt)
                #pragma unroll
                for (int nt = 0; nt < 4; ++nt) {
                    mma_bf(acc[mt][nt], ah[mt], bh[nt]);
                    mma_bf(acc[mt][nt], ah[mt], bl[nt]);
                    mma_bf(acc[mt][nt], al[mt], bh[nt]);
                }
        }
        __syncthreads();
        if (s + NSTAGE < nstages) load_stage(s + NSTAGE);
        cp_commit();
    }

    // ---- epilogue ----
    const int g4 = lane >> 2, t4 = lane & 3;
    #pragma unroll
    for (int mt = 0; mt < 4; ++mt) {
        #pragma unroll
        for (int dr = 0; dr < 2; ++dr) {
            const int o = m0 + wm * 64 + mt * 16 + g4 + dr * 8;
            if (mode == 3 && o >= 32) continue;
            const float bv = bias[o];
            float gv = 0.f, bev = 0.f;
            if (mode != 0) { gv = gamma[o]; bev = beta[o]; }
            const int jo = o >> 6, co = o & 63;
            #pragma unroll
            for (int nt = 0; nt < 4; ++nt) {
                #pragma unroll
                for (int dn = 0; dn < 2; ++dn) {
                    const float sv = acc[mt][nt][dr * 2 + dn] + bv;
                    const int n = n0 + wn * 32 + nt * 8 + t4 * 2 + dn;
                    if (mode == 0) {
                        out32[(size_t)n * 256 + o] = sv;
                        __nv_bfloat16 h, l; split_bf(sv, h, l);
                        const size_t base = ((size_t)n * nchO + jo) * 128;
                        actOut[base + co] = h; actOut[base + 64 + co] = l;
                    } else if (mode == 1) {
                        const float v = fmaxf(sv * gv + bev, 0.f);
                        __nv_bfloat16 h, l; split_bf(v, h, l);
                        const size_t base = ((size_t)n * nchO + jo) * 128;
                        actOut[base + co] = h; actOut[base + 64 + co] = l;
                    } else if (mode == 2) {
                        const float v = fmaxf(sv * gv + bev, 0.f) + dres[(size_t)n * 256 + o];
                        __nv_bfloat16 h, l; split_bf(v, h, l);
                        const size_t base = ((size_t)n * nchO + jo) * 128;
                        actOut[base + co] = h; actOut[base + 64 + co] = l;
                    } else {
                        const int b = n / 60, gg = n - b * 60;
                        out32[(size_t)n * 32 + o] =
                            fmaxf(sv * gv + bev, 0.f) + feats[(size_t)b * 1920 + o * 60 + gg];
                    }
                }
            }
        }
    }
}

// ---- finalize: epT[(b,g)][32] -> inv + normalized eqv [b][c][g] ----
__global__ __launch_bounds__(64) void finalize_t(
    const float* __restrict__ epT, float* __restrict__ e_store,
    float* __restrict__ out_eqv, float* __restrict__ out_inv)
{
    __shared__ float s[1920];
    __shared__ float norms[60];
    __shared__ float invv[32];
    __shared__ float ninv;
    const int b = blockIdx.x, t = threadIdx.x;

    for (int i = t; i < 1920; i += 64) s[i] = epT[(size_t)b * 1920 + i];
    __syncthreads();
    if (t < 60) {
        float a = 0.f;
        #pragma unroll
        for (int c = 0; c < 32; ++c) { float v = s[t * 32 + c]; a += v * v; }
        norms[t] = fmaxf(sqrtf(a), 1e-4f);
    }
    if (t < 32) {
        float a = 0.f;
        for (int g = 0; g < 60; ++g) a += s[g * 32 + t];
        invv[t] = a * (1.f / 60.f);
    }
    __syncthreads();
    if (t == 0) {
        float a = 0.f;
        #pragma unroll
        for (int c = 0; c < 32; ++c) a += invv[c] * invv[c];
        ninv = fmaxf(sqrtf(a), 1e-4f);
    }
    __syncthreads();
    if (t < 32) out_inv[b * 32 + t] = invv[t] / ninv;
    for (int i = t; i < 1920; i += 64) {
        const int g = i >> 5, c = i & 31;
        const float v = s[i] / norms[g];
        const size_t oi = (size_t)b * 1920 + c * 60 + g;
        out_eqv[oi] = v;
        e_store[oi] = v;
    }
}

// ---- des2dr ----
__global__ __launch_bounds__(64) void des2dr_kernel(
    const float* __restrict__ e0, const float* __restrict__ e1,
    const int* __restrict__ permu, int* __restrict__ pre)
{
    __shared__ float s0[1920], s1[1920];
    __shared__ float cor[60];
    __shared__ int sp[3600];
    const int b = blockIdx.x, t = threadIdx.x;

    for (int i = t; i < 1920; i += 64) {
        s0[i] = e0[(size_t)b * 1920 + i];
        s1[i] = e1[(size_t)b * 1920 + i];
    }
    for (int i = t; i < 3600; i += 64) sp[i] = permu[i];
    __syncthreads();

    if (t < 60) {
        float a = 0.f;
        for (int g = 0; g < 60; ++g) {
            const int p = sp[t * 60 + g];
            #pragma unroll 8
            for (int f = 0; f < 32; ++f) a += s0[f * 60 + p] * s1[f * 60 + g];
        }
        cor[t] = a;
    }
    __syncthreads();
    if (t == 0) {
        float best = cor[0]; int bi = 0;
        for (int a = 1; a < 60; ++a) if (cor[a] > best) { best = cor[a]; bi = a; }
        pre[b] = bi;
    }
}

// ---- ability + integer outputs ----
__global__ __launch_bounds__(256) void final_kernel(
    const int* __restrict__ pre, const int* __restrict__ truei,
    float* __restrict__ out)
{
    __shared__ int cnt[256];
    const int t = threadIdx.x;
    cnt[t] = (pre[t] == truei[t]) ? 1 : 0;
    __syncthreads();
    for (int s = 128; s > 0; s >>= 1) {
        if (t < s) cnt[t] += cnt[t + s];
        __syncthreads();
    }
    if (t == 0) out[OFF_AB] = (float)cnt[0] / 256.f;
    out[OFF_TI + t] = (float)truei[t];
    out[OFF_PI + t] = (float)pre[t];
}

// ---------------------------------------------------------------------------
extern "C" void kernel_launch(void* const* d_in, const int* in_sizes, int n_in,
                              void* d_out, int out_size)
{
    const float* feats0 = (const float*)d_in[0];
    const float* feats1 = (const float*)d_in[1];
    const int*   truei  = (const int*)  d_in[2];
    const int*   nei    = (const int*)  d_in[3];
    const int*   permu  = (const int*)  d_in[4];
    const float* W_in = (const float*)d_in[5];  const float* b_in = (const float*)d_in[6];
    const float* W1   = (const float*)d_in[7];  const float* b1   = (const float*)d_in[8];
    const float* g1   = (const float*)d_in[9];  const float* be1  = (const float*)d_in[10];
    const float* W2   = (const float*)d_in[11]; const float* b2   = (const float*)d_in[12];
    const float* g2   = (const float*)d_in[13]; const float* be2  = (const float*)d_in[14];
    const float* Wo   = (const float*)d_in[15]; const float* bo   = (const float*)d_in[16];
    const float* go   = (const float*)d_in[17]; const float* beo  = (const float*)d_in[18];
    float* out = (float*)d_out;

    __nv_bfloat16 *WpI, *Wp1, *Wp2, *WpO, *fP, *dP, *f1P, *d2P;
    float *dT32, *epT, *e0, *e1;
    int* pre;
    cudaGetSymbolAddress((void**)&WpI,  g_WpI);
    cudaGetSymbolAddress((void**)&Wp1,  g_Wp1);
    cudaGetSymbolAddress((void**)&Wp2,  g_Wp2);
    cudaGetSymbolAddress((void**)&WpO,  g_WpO);
    cudaGetSymbolAddress((void**)&fP,   g_fP);
    cudaGetSymbolAddress((void**)&dP,   g_dP);
    cudaGetSymbolAddress((void**)&f1P,  g_f1P);
    cudaGetSymbolAddress((void**)&d2P,  g_d2P);
    cudaGetSymbolAddress((void**)&dT32, g_dT32);
    cudaGetSymbolAddress((void**)&epT,  g_epT);
    cudaGetSymbolAddress((void**)&e0,   g_e0);
    cudaGetSymbolAddress((void**)&e1,   g_e1);
    cudaGetSymbolAddress((void**)&pre,  g_pre);

    cudaFuncSetAttribute(gf_gemm, cudaFuncAttributeMaxDynamicSharedMemorySize, SMEM_DYN);

    cudaMemcpyAsync(out + OFF_F0, feats0, (size_t)491520 * 4, cudaMemcpyDeviceToDevice, 0);
    cudaMemcpyAsync(out + OFF_F1, feats1, (size_t)491520 * 4, cudaMemcpyDeviceToDevice, 0);

    // weight prep: total threads = O * nstages * 64
    prep_w<<<(256 * 13 * 64) / 256, 256>>>(WpI, W_in, 256, 32, 13);
    prep_w<<<(512 * 52 * 64) / 256, 256>>>(Wp1, W1, 512, 256, 52);
    prep_w<<<(256 * 104 * 64) / 256, 256>>>(Wp2, W2, 256, 512, 104);
    prep_w<<<(128 * 52 * 64) / 256, 256>>>(WpO, Wo, 32, 256, 52);

    auto run_net = [&](const float* feats, float* e_store, float* out_eqv, float* out_inv) {
        prep_feats<<<(NTOT * 64) / 256, 256>>>(fP, feats);
        // conv_in: Cin=64(pad), O=256 -> mode 0 (write dT32 + dP)
        gf_gemm<<<dim3(120, 2), 256, SMEM_DYN>>>(WpI, fP, 1, 13, nei, 0,
            b_in, b_in, b_in, dT32, feats, dT32, dP, 4);
        // layer1: Cin=256, O=512 -> mode 1 (BN+ReLU -> f1P)
        gf_gemm<<<dim3(120, 4), 256, SMEM_DYN>>>(Wp1, dP, 4, 52, nei, 1,
            b1, g1, be1, dT32, feats, dT32, f1P, 8);
        // layer2: Cin=512, O=256 -> mode 2 (BN+ReLU + residual dT32 -> d2P)
        gf_gemm<<<dim3(120, 2), 256, SMEM_DYN>>>(Wp2, f1P, 8, 104, nei, 2,
            b2, g2, be2, dT32, feats, dT32, d2P, 4);
        // conv_out: Cin=256, O=32(pad128) -> mode 3 (BN+ReLU + feats -> epT)
        gf_gemm<<<dim3(120, 1), 256, SMEM_DYN>>>(WpO, d2P, 4, 52, nei, 3,
            bo, go, beo, dT32, feats, epT, dP, 4);
        finalize_t<<<BATCH, 64>>>(epT, e_store, out_eqv, out_inv);
    };

    run_net(feats0, e0, out + OFF_E0, out + OFF_I0);
    run_net(feats1, e1, out + OFF_E1, out + OFF_I1);

    des2dr_kernel<<<BATCH, 64>>>(e0, e1, permu, pre);
    final_kernel<<<1, 256>>>(pre, truei, out);
}